// round 2
// baseline (speedup 1.0000x reference)
#include <cuda_runtime.h>
#include <cuda_bf16.h>
#include <cstdint>

#define BATCH 128
#define SEQ   2048
#define INF   128
#define HID   256
#define OUTF  128
#define KTOT  384          // INF + HID
#define CHUNKS 24          // KTOT / 16
#define RS    400          // B-buffer row stride in halves (bank-conflict-free for LDS.64)
#define NROW  8            // N dimension of mma (only col 0 real)

// fragment-permutation: position of k%16 inside a 16-half chunk so that
// lane q (=tid%4) reads its 4 B-fragment halves {2q,2q+1,2q+8,2q+9} with one LDS.64
__device__ __forceinline__ int posmap(int i) {
    return (i & 1) + ((i >> 1) & 3) * 4 + ((i >> 3) & 1) * 2;
}

__device__ __forceinline__ uint32_t packbf(float lo, float hi) {
    __nv_bfloat162 v = __floats2bfloat162_rn(lo, hi);
    return *reinterpret_cast<uint32_t*>(&v);
}

__device__ __forceinline__ void mma16816(float& c0, float& c1, float& c2, float& c3,
                                         uint32_t a0, uint32_t a1, uint32_t a2, uint32_t a3,
                                         uint32_t b0, uint32_t b1) {
    asm volatile(
        "mma.sync.aligned.m16n8k16.row.col.f32.bf16.bf16.f32 "
        "{%0,%1,%2,%3}, {%4,%5,%6,%7}, {%8,%9}, {%0,%1,%2,%3};\n"
        : "+f"(c0), "+f"(c1), "+f"(c2), "+f"(c3)
        : "r"(a0), "r"(a1), "r"(a2), "r"(a3), "r"(b0), "r"(b1));
}

__global__ void __launch_bounds__(256, 1)
elman_kernel(const float* __restrict__ x,
             const float* __restrict__ Win,
             const float* __restrict__ bin,
             const float* __restrict__ Wrec,
             const float* __restrict__ Wout,
             const float* __restrict__ bout,
             float* __restrict__ out)
{
    __shared__ __align__(16) __nv_bfloat16 sB[2][NROW * RS]; // ping-pong B operand [8 x 400]
    __shared__ float z_s[HID];
    __shared__ float h32_s[HID];
    __shared__ float bin_s[HID];

    const int tid  = threadIdx.x;
    const int b    = blockIdx.x;
    const int warp = tid >> 5;
    const int lane = tid & 31;
    const int qr   = lane >> 2;        // 0..7  (row-within-tile / B n-index)
    const int qc   = (lane & 3) * 2;   // 0,2,4,6 (k base within chunk)

    // zero both B buffers (rows 1..7 stay zero forever -> dummy mma columns)
    for (int i = tid; i < 2 * NROW * RS; i += 256)
        ((__nv_bfloat16*)sB)[i] = __float2bfloat16(0.f);
    if (tid < HID) bin_s[tid] = bin[tid];

    // ---- load persistent A fragments: A_cat = [W_in | W_rec], rows=hidden j, cols=k ----
    uint32_t Af[CHUNKS][2][4];
#pragma unroll
    for (int kc = 0; kc < CHUNKS; kc++) {
#pragma unroll
        for (int m = 0; m < 2; m++) {
            const int r = warp * 32 + m * 16 + qr;
            const int c = kc * 16 + qc;
            // A_cat(j,k) = k<128 ? Win[j][k] : Wrec[j][k-128]; split is chunk-aligned
            const float* rowA  = (c < INF) ? (Win + (size_t)r * INF + c)
                                           : (Wrec + (size_t)r * HID + (c - INF));
            const float* rowA8 = (c < INF) ? (Win + (size_t)(r + 8) * INF + c)
                                           : (Wrec + (size_t)(r + 8) * HID + (c - INF));
            Af[kc][m][0] = packbf(rowA[0],  rowA[1]);
            Af[kc][m][1] = packbf(rowA8[0], rowA8[1]);
            Af[kc][m][2] = packbf(rowA[8],  rowA[9]);
            Af[kc][m][3] = packbf(rowA8[8], rowA8[9]);
        }
    }

    // ---- load x_0 into buffer 0 (h region stays zero = h_init) ----
    const float* xb = x + (size_t)b * SEQ * INF;
    if (tid < INF) {
        float v = xb[tid];
        sB[0][(tid >> 4) * 16 + posmap(tid & 15)] = __float2bfloat16(v);
    }

    float cacc[2][4];
#pragma unroll
    for (int m = 0; m < 2; m++)
#pragma unroll
        for (int i = 0; i < 4; i++) cacc[m][i] = 0.f;

    // per-lane B-fragment base pointers (one LDS.64 per chunk)
    const uint2* bp0 = reinterpret_cast<const uint2*>(&sB[0][qr * RS + (lane & 3) * 4]);
    const uint2* bp1 = reinterpret_cast<const uint2*>(&sB[1][qr * RS + (lane & 3) * 4]);

    __syncthreads();

    for (int t = 0; t < SEQ; t++) {
        const int cur = t & 1;
        const int nxt = cur ^ 1;
        const uint2* bp = cur ? bp1 : bp0;

        // prefetch next timestep's x (consumed after bar, hidden under mma)
        float xv = 0.f;
        if (tid < INF && t + 1 < SEQ) xv = xb[(size_t)(t + 1) * INF + tid];

        // ---- mma phase: z = A_cat @ [x_t ; h] over 24 k16-chunks ----
        uint2 bv = bp[0];
#pragma unroll
        for (int kc = 0; kc < CHUNKS; kc++) {
            uint2 bvn = make_uint2(0u, 0u);
            if (kc + 1 < CHUNKS) bvn = bp[(kc + 1) * 4];
            mma16816(cacc[0][0], cacc[0][1], cacc[0][2], cacc[0][3],
                     Af[kc][0][0], Af[kc][0][1], Af[kc][0][2], Af[kc][0][3], bv.x, bv.y);
            mma16816(cacc[1][0], cacc[1][1], cacc[1][2], cacc[1][3],
                     Af[kc][1][0], Af[kc][1][1], Af[kc][1][2], Af[kc][1][3], bv.x, bv.y);
            bv = bvn;
        }

        // ---- extract column 0 (lanes with tid%4==0 hold it in c0 and c2) ----
        if ((lane & 3) == 0) {
            const int rbase = warp * 32 + qr;
            z_s[rbase]      = cacc[0][0];
            z_s[rbase + 8]  = cacc[0][2];
            z_s[rbase + 16] = cacc[1][0];
            z_s[rbase + 24] = cacc[1][2];
        }
#pragma unroll
        for (int m = 0; m < 2; m++)
#pragma unroll
            for (int i = 0; i < 4; i++) cacc[m][i] = 0.f;

        __syncthreads();

        // ---- pointwise: sigmoid, write h (bf16) + x_{t+1} into next buffer ----
        {
            const float z = z_s[tid] + bin_s[tid];
            const float h = __fdividef(1.f, 1.f + __expf(-z));
            h32_s[tid] = h;
            const int i = tid & 15;
            sB[nxt][(8 + (tid >> 4)) * 16 + posmap(i)] = __float2bfloat16(h);
            if (tid < INF)
                sB[nxt][(tid >> 4) * 16 + posmap(i)] = __float2bfloat16(xv);
        }
        __syncthreads();
    }

    // ---- final projection: y[b] = h @ Wout^T + bout (fp32) ----
    {
        const int o    = tid & (OUTF - 1);
        const int half = tid >> 7;
        const float* wrow = Wout + (size_t)o * HID + half * 128;
        const float* hh   = h32_s + half * 128;
        float acc = 0.f;
#pragma unroll 8
        for (int k = 0; k < 128; k++) acc += hh[k] * __ldg(&wrow[k]);
        z_s[tid] = acc;
    }
    __syncthreads();
    if (tid < OUTF)
        out[(size_t)b * OUTF + tid] = z_s[tid] + z_s[tid + 128] + bout[tid];
}

extern "C" void kernel_launch(void* const* d_in, const int* in_sizes, int n_in,
                              void* d_out, int out_size)
{
    const float* x    = (const float*)d_in[0];
    const float* Win  = (const float*)d_in[1];
    const float* bin  = (const float*)d_in[2];
    const float* Wrec = (const float*)d_in[3];
    const float* Wout = (const float*)d_in[4];
    const float* bout = (const float*)d_in[5];
    float* out = (float*)d_out;

    elman_kernel<<<BATCH, 256>>>(x, Win, bin, Wrec, Wout, bout, out);
}